// round 1
// baseline (speedup 1.0000x reference)
#include <cuda_runtime.h>
#include <cstdint>
#include <cstddef>

#define BATCH 8192
#define NREC  1024
#define HID   2048

#define BM 128
#define BN 128
#define BK 32

// Shared-memory strides (floats), padded for conflict-free mma fragment loads
#define SA_STRIDE 36        // 128 rows x (32 + 4 pad)  -> bank = 4g+t : conflict free
#define SB_STRIDE 136       // 32 rows x (128 + 8 pad)  -> bank = 8t+g : conflict free
#define SA_STAGE (BM * SA_STRIDE)   // 4608 floats
#define SB_STAGE (BK * SB_STRIDE)   // 4352 floats

extern __shared__ float smem[];

__device__ __forceinline__ uint32_t f2tf32(float x) {
    uint32_t r;
    asm("cvt.rna.tf32.f32 %0, %1;" : "=r"(r) : "f"(x));
    return r;
}

__device__ __forceinline__ void mma8(float* d, const uint32_t* a, const uint32_t* b) {
    asm volatile(
        "mma.sync.aligned.m16n8k8.row.col.f32.tf32.tf32.f32 "
        "{%0,%1,%2,%3}, {%4,%5,%6,%7}, {%8,%9}, {%0,%1,%2,%3};\n"
        : "+f"(d[0]), "+f"(d[1]), "+f"(d[2]), "+f"(d[3])
        : "r"(a[0]), "r"(a[1]), "r"(a[2]), "r"(a[3]), "r"(b[0]), "r"(b[1]));
}

__device__ __forceinline__ void cp16(float* s, const float* g) {
    uint32_t sa = (uint32_t)__cvta_generic_to_shared(s);
    asm volatile("cp.async.cg.shared.global [%0], [%1], 16;\n" :: "r"(sa), "l"(g));
}
__device__ __forceinline__ void cp_commit() { asm volatile("cp.async.commit_group;\n"); }
__device__ __forceinline__ void cp_wait1()  { asm volatile("cp.async.wait_group 1;\n"); }
__device__ __forceinline__ void cp_wait0()  { asm volatile("cp.async.wait_group 0;\n"); }

// ===========================================================================
// GEMM1: t = U[B,NREC] @ Bmat[NREC,HID]; epilogue x = lambda*state + gamma*t
// blockIdx.z selects re (0) / im (1) branch.
// ===========================================================================
__global__ __launch_bounds__(256, 1) void lru_gemm1(
    const float* __restrict__ U,
    const float* __restrict__ Bre, const float* __restrict__ Bim,
    const float* __restrict__ Sre, const float* __restrict__ Sim,
    const float* __restrict__ nu,  const float* __restrict__ theta,
    const float* __restrict__ gam,
    float* __restrict__ Xre, float* __restrict__ Xim)
{
    const int n0 = blockIdx.x * BN;      // over HID
    const int m0 = blockIdx.y * BM;      // over BATCH
    const int z  = blockIdx.z;
    const float* __restrict__ Bmat = z ? Bim : Bre;

    float* sA = smem;                    // 2 stages
    float* sB = smem + 2 * SA_STAGE;

    const int tid  = threadIdx.x;
    const int warp = tid >> 5, lane = tid & 31;
    const int g = lane >> 2, t = lane & 3;
    const int wm = (warp >> 2) * 64;     // 2 warps in M
    const int wn = (warp & 3) * 32;      // 4 warps in N

    float acc[4][4][4];
    #pragma unroll
    for (int i = 0; i < 4; i++)
        #pragma unroll
        for (int j = 0; j < 4; j++)
            #pragma unroll
            for (int r = 0; r < 4; r++) acc[i][j][r] = 0.f;

    auto loadA = [&](int stage, int k0) {
        #pragma unroll
        for (int i = 0; i < 4; i++) {
            int c = tid + i * 256;               // 0..1023 chunks of 16B
            int row = c >> 3, cc = (c & 7) * 4;
            cp16(sA + stage * SA_STAGE + row * SA_STRIDE + cc,
                 U + (size_t)(m0 + row) * NREC + k0 + cc);
        }
    };
    auto loadB = [&](int stage, int k0) {
        #pragma unroll
        for (int i = 0; i < 4; i++) {
            int c = tid + i * 256;
            int row = c >> 5, cc = (c & 31) * 4;
            cp16(sB + stage * SB_STAGE + row * SB_STRIDE + cc,
                 Bmat + (size_t)(k0 + row) * HID + n0 + cc);
        }
    };

    loadA(0, 0); loadB(0, 0); cp_commit();

    const int NKT = NREC / BK;   // 32
    for (int kt = 0; kt < NKT; kt++) {
        int cur = kt & 1;
        if (kt + 1 < NKT) {
            loadA(cur ^ 1, (kt + 1) * BK);
            loadB(cur ^ 1, (kt + 1) * BK);
            cp_commit();
            cp_wait1();
        } else {
            cp_wait0();
        }
        __syncthreads();
        const float* sAc = sA + cur * SA_STAGE;
        const float* sBc = sB + cur * SB_STAGE;
        #pragma unroll
        for (int ks = 0; ks < 4; ks++) {
            int kk = ks * 8;
            uint32_t a[4][4], b[4][2];
            #pragma unroll
            for (int i = 0; i < 4; i++) {
                int r = wm + i * 16 + g;
                a[i][0] = f2tf32(sAc[r * SA_STRIDE + kk + t]);
                a[i][1] = f2tf32(sAc[(r + 8) * SA_STRIDE + kk + t]);
                a[i][2] = f2tf32(sAc[r * SA_STRIDE + kk + t + 4]);
                a[i][3] = f2tf32(sAc[(r + 8) * SA_STRIDE + kk + t + 4]);
            }
            #pragma unroll
            for (int j = 0; j < 4; j++) {
                int cn = wn + j * 8 + g;
                b[j][0] = f2tf32(sBc[(kk + t) * SB_STRIDE + cn]);
                b[j][1] = f2tf32(sBc[(kk + t + 4) * SB_STRIDE + cn]);
            }
            #pragma unroll
            for (int i = 0; i < 4; i++)
                #pragma unroll
                for (int j = 0; j < 4; j++)
                    mma8(acc[i][j], a[i], b[j]);
        }
        __syncthreads();
    }

    // Epilogue: precompute lambda / gamma for this block's 128 H-columns
    float* sLr = smem;          // smem no longer needed for tiles
    float* sLi = smem + 128;
    float* sG  = smem + 256;
    if (tid < 128) {
        int h = n0 + tid;
        float e = expf(-expf(nu[h]));
        sLr[tid] = e * cosf(theta[h]);
        sLi[tid] = e * sinf(theta[h]);
        sG[tid]  = gam[h];
    }
    __syncthreads();

    float* __restrict__ Xout = z ? Xim : Xre;
    #pragma unroll
    for (int i = 0; i < 4; i++) {
        int r0 = m0 + wm + i * 16 + g;
        #pragma unroll
        for (int j = 0; j < 4; j++) {
            int cl = wn + j * 8 + 2 * t;
            int c  = n0 + cl;
            float lr0 = sLr[cl],     li0 = sLi[cl],     g0 = sG[cl];
            float lr1 = sLr[cl + 1], li1 = sLi[cl + 1], g1 = sG[cl + 1];
            #pragma unroll
            for (int rr = 0; rr < 2; rr++) {
                int r = r0 + rr * 8;
                size_t off = (size_t)r * HID + c;
                float2 sre = *(const float2*)(Sre + off);
                float2 sim = *(const float2*)(Sim + off);
                float t0 = acc[i][j][rr * 2 + 0];
                float t1 = acc[i][j][rr * 2 + 1];
                float2 o;
                if (z == 0) {
                    o.x = sre.x * lr0 - sim.x * li0 + g0 * t0;
                    o.y = sre.y * lr1 - sim.y * li1 + g1 * t1;
                } else {
                    o.x = sre.x * li0 + sim.x * lr0 + g0 * t0;
                    o.y = sre.y * li1 + sim.y * lr1 + g1 * t1;
                }
                *(float2*)(Xout + off) = o;
            }
        }
    }
}

// ===========================================================================
// GEMM2: y = Xre[B,HID] @ Cre[HID,NREC] - Xim @ Cim + D * U
// ===========================================================================
__global__ __launch_bounds__(256, 1) void lru_gemm2(
    const float* __restrict__ Xre, const float* __restrict__ Xim,
    const float* __restrict__ Cre, const float* __restrict__ Cim,
    const float* __restrict__ Dv,  const float* __restrict__ U,
    float* __restrict__ Y)
{
    const int n0 = blockIdx.x * BN;      // over NREC
    const int m0 = blockIdx.y * BM;      // over BATCH

    float* sAre = smem;                          // 2 stages each
    float* sAim = smem + 2 * SA_STAGE;
    float* sBre = smem + 4 * SA_STAGE;
    float* sBim = smem + 4 * SA_STAGE + 2 * SB_STAGE;

    const int tid  = threadIdx.x;
    const int warp = tid >> 5, lane = tid & 31;
    const int g = lane >> 2, t = lane & 3;
    const int wm = (warp >> 2) * 64;
    const int wn = (warp & 3) * 32;

    float acc[4][4][4];
    #pragma unroll
    for (int i = 0; i < 4; i++)
        #pragma unroll
        for (int j = 0; j < 4; j++)
            #pragma unroll
            for (int r = 0; r < 4; r++) acc[i][j][r] = 0.f;

    auto loadStage = [&](int stage, int k0) {
        #pragma unroll
        for (int i = 0; i < 4; i++) {
            int c = tid + i * 256;
            int row = c >> 3, cc = (c & 7) * 4;
            size_t goff = (size_t)(m0 + row) * HID + k0 + cc;
            cp16(sAre + stage * SA_STAGE + row * SA_STRIDE + cc, Xre + goff);
            cp16(sAim + stage * SA_STAGE + row * SA_STRIDE + cc, Xim + goff);
        }
        #pragma unroll
        for (int i = 0; i < 4; i++) {
            int c = tid + i * 256;
            int row = c >> 5, cc = (c & 31) * 4;
            size_t goff = (size_t)(k0 + row) * NREC + n0 + cc;
            cp16(sBre + stage * SB_STAGE + row * SB_STRIDE + cc, Cre + goff);
            cp16(sBim + stage * SB_STAGE + row * SB_STRIDE + cc, Cim + goff);
        }
    };

    loadStage(0, 0); cp_commit();

    const int NKT = HID / BK;    // 64
    for (int kt = 0; kt < NKT; kt++) {
        int cur = kt & 1;
        if (kt + 1 < NKT) {
            loadStage(cur ^ 1, (kt + 1) * BK);
            cp_commit();
            cp_wait1();
        } else {
            cp_wait0();
        }
        __syncthreads();
        const float* sArc = sAre + cur * SA_STAGE;
        const float* sAic = sAim + cur * SA_STAGE;
        const float* sBrc = sBre + cur * SB_STAGE;
        const float* sBic = sBim + cur * SB_STAGE;
        #pragma unroll
        for (int ks = 0; ks < 4; ks++) {
            int kk = ks * 8;
            uint32_t ar[4][4], ai[4][4], br[4][2], bi[4][2];
            #pragma unroll
            for (int i = 0; i < 4; i++) {
                int r = wm + i * 16 + g;
                ar[i][0] = f2tf32(sArc[r * SA_STRIDE + kk + t]);
                ar[i][1] = f2tf32(sArc[(r + 8) * SA_STRIDE + kk + t]);
                ar[i][2] = f2tf32(sArc[r * SA_STRIDE + kk + t + 4]);
                ar[i][3] = f2tf32(sArc[(r + 8) * SA_STRIDE + kk + t + 4]);
                // negate imaginary-part A so a single accumulator does re - im
                ai[i][0] = f2tf32(-sAic[r * SA_STRIDE + kk + t]);
                ai[i][1] = f2tf32(-sAic[(r + 8) * SA_STRIDE + kk + t]);
                ai[i][2] = f2tf32(-sAic[r * SA_STRIDE + kk + t + 4]);
                ai[i][3] = f2tf32(-sAic[(r + 8) * SA_STRIDE + kk + t + 4]);
            }
            #pragma unroll
            for (int j = 0; j < 4; j++) {
                int cn = wn + j * 8 + g;
                br[j][0] = f2tf32(sBrc[(kk + t) * SB_STRIDE + cn]);
                br[j][1] = f2tf32(sBrc[(kk + t + 4) * SB_STRIDE + cn]);
                bi[j][0] = f2tf32(sBic[(kk + t) * SB_STRIDE + cn]);
                bi[j][1] = f2tf32(sBic[(kk + t + 4) * SB_STRIDE + cn]);
            }
            #pragma unroll
            for (int i = 0; i < 4; i++)
                #pragma unroll
                for (int j = 0; j < 4; j++) {
                    mma8(acc[i][j], ar[i], br[j]);
                    mma8(acc[i][j], ai[i], bi[j]);
                }
        }
        __syncthreads();
    }

    // Epilogue: y = acc + D[c] * U[r,c]
    float* sD = smem;
    if (tid < 128) sD[tid] = Dv[n0 + tid];
    __syncthreads();

    #pragma unroll
    for (int i = 0; i < 4; i++) {
        int r0 = m0 + wm + i * 16 + g;
        #pragma unroll
        for (int j = 0; j < 4; j++) {
            int cl = wn + j * 8 + 2 * t;
            int c  = n0 + cl;
            float d0 = sD[cl], d1 = sD[cl + 1];
            #pragma unroll
            for (int rr = 0; rr < 2; rr++) {
                int r = r0 + rr * 8;
                size_t off = (size_t)r * NREC + c;
                float2 u = *(const float2*)(U + off);
                float2 o;
                o.x = acc[i][j][rr * 2 + 0] + d0 * u.x;
                o.y = acc[i][j][rr * 2 + 1] + d1 * u.y;
                *(float2*)(Y + off) = o;
            }
        }
    }
}

// ===========================================================================
extern "C" void kernel_launch(void* const* d_in, const int* in_sizes, int n_in,
                              void* d_out, int out_size)
{
    const float* U   = (const float*)d_in[0];
    const float* Sre = (const float*)d_in[1];
    const float* Sim = (const float*)d_in[2];
    const float* Bre = (const float*)d_in[3];
    const float* Bim = (const float*)d_in[4];
    const float* Cre = (const float*)d_in[5];
    const float* Cim = (const float*)d_in[6];
    const float* Dv  = (const float*)d_in[7];
    const float* nu  = (const float*)d_in[8];
    const float* th  = (const float*)d_in[9];
    const float* gm  = (const float*)d_in[10];

    float* Y   = (float*)d_out;
    float* Xre = Y + (size_t)BATCH * NREC;
    float* Xim = Xre + (size_t)BATCH * HID;

    const int smem1 = 2 * (SA_STAGE + SB_STAGE) * (int)sizeof(float);   // 71680
    const int smem2 = (4 * SA_STAGE + 4 * SB_STAGE) * (int)sizeof(float); // 143360
    cudaFuncSetAttribute(lru_gemm1, cudaFuncAttributeMaxDynamicSharedMemorySize, smem1);
    cudaFuncSetAttribute(lru_gemm2, cudaFuncAttributeMaxDynamicSharedMemorySize, smem2);

    dim3 g1(HID / BN, BATCH / BM, 2);
    lru_gemm1<<<g1, 256, smem1>>>(U, Bre, Bim, Sre, Sim, nu, th, gm, Xre, Xim);

    dim3 g2(NREC / BN, BATCH / BM);
    lru_gemm2<<<g2, 256, smem2>>>(Xre, Xim, Cre, Cim, Dv, U, Y);
}

// round 3
// speedup vs baseline: 1.5918x; 1.5918x over previous
#include <cuda_runtime.h>
#include <cstdint>
#include <cstddef>

#define BATCH 8192
#define NREC  1024
#define HID   2048

#define BK 32
#define SA 36     // A smem row stride (floats): 128 rows x (32+4)
#define SB 136    // B smem row stride (floats): 32 rows x (128+8)
#define A_TILE (128 * SA)   // 4608 floats
#define B_TILE (BK * SB)    // 4352 floats

extern __shared__ float smem[];

// ---------------- scratch weights (prepped: rna-rounded, n-permuted, Cim negated) ----
__device__ float g_B[2u * NREC * HID];             // [Bre'|Bim'] each [NREC k][HID n]
__device__ float g_C[2u * HID * NREC];             // [Cre'|Cimneg'] each [HID k][NREC n]

__device__ __forceinline__ uint32_t f2tf32(float x) {
    uint32_t r; asm("cvt.rna.tf32.f32 %0, %1;" : "=r"(r) : "f"(x)); return r;
}

__device__ __forceinline__ void mma8(float* d, const uint32_t* a, uint32_t b0, uint32_t b1) {
    asm volatile(
        "mma.sync.aligned.m16n8k8.row.col.f32.tf32.tf32.f32 "
        "{%0,%1,%2,%3}, {%4,%5,%6,%7}, {%8,%9}, {%0,%1,%2,%3};\n"
        : "+f"(d[0]), "+f"(d[1]), "+f"(d[2]), "+f"(d[3])
        : "r"(a[0]), "r"(a[1]), "r"(a[2]), "r"(a[3]), "r"(b0), "r"(b1));
}

__device__ __forceinline__ void cp16(float* s, const float* g) {
    uint32_t sa = (uint32_t)__cvta_generic_to_shared(s);
    asm volatile("cp.async.cg.shared.global [%0], [%1], 16;\n" :: "r"(sa), "l"(g));
}
__device__ __forceinline__ void cp_commit() { asm volatile("cp.async.commit_group;\n"); }
__device__ __forceinline__ void cp_wait1()  { asm volatile("cp.async.wait_group 1;\n"); }
__device__ __forceinline__ void cp_wait0()  { asm volatile("cp.async.wait_group 0;\n"); }

// ---------------- prep: rna-round, permute n within 32-blocks, optional negate -------
// src/dst: [K][N] row-major. dst col (base + p) <- src col (base + (p&3)*8 + (p>>2))
__global__ __launch_bounds__(256) void prep_w(const float* __restrict__ src,
                                              float* __restrict__ dst,
                                              int N, int total, float sign)
{
    int idx = blockIdx.x * 256 + threadIdx.x;
    if (idx >= total) return;
    int row = idx / N, l = idx % N;
    int base = l & ~31, p = l & 31;
    int sl = base + ((p & 3) * 8) + (p >> 2);
    float v = sign * src[(size_t)row * N + sl];
    dst[idx] = __uint_as_float(f2tf32(v));
}

// =====================================================================================
// GEMM1: T = U[B,NREC] @ {Bre',Bim'}[NREC,HID];  X = lam*S + gamma*T  (re+im fused)
// block tile 128(M) x 128(N), 256 threads, warp tile 64x32, 3-stage cp.async
// =====================================================================================
__global__ __launch_bounds__(256, 1) void lru_g1(
    const float* __restrict__ U,
    const float* __restrict__ BreP, const float* __restrict__ BimP,
    const float* __restrict__ Sre, const float* __restrict__ Sim,
    const float* __restrict__ nu,  const float* __restrict__ theta,
    const float* __restrict__ gam,
    float* __restrict__ Xre, float* __restrict__ Xim)
{
    const int n0 = blockIdx.x * 128;     // HID
    const int m0 = blockIdx.y * 128;     // BATCH
    const int tid = threadIdx.x, warp = tid >> 5, lane = tid & 31;
    const int g = lane >> 2, t = lane & 3;
    const int wm = (warp >> 2) * 64, wn = (warp & 3) * 32;

    // stage layout: [A | Bre | Bim] x 3
    const int ST = A_TILE + 2 * B_TILE;            // 13312 floats
    float* sA  = smem;
    float* sBr = smem + A_TILE;
    float* sBi = smem + A_TILE + B_TILE;

    float ar[4][4][4], ai[4][4][4];
    #pragma unroll
    for (int i = 0; i < 4; i++)
        #pragma unroll
        for (int j = 0; j < 4; j++)
            #pragma unroll
            for (int r = 0; r < 4; r++) { ar[i][j][r] = 0.f; ai[i][j][r] = 0.f; }

    auto loadStage = [&](int s, int k0) {
        float* a  = sA  + s * ST;
        float* br = sBr + s * ST;
        float* bi = sBi + s * ST;
        #pragma unroll
        for (int i = 0; i < 4; i++) {
            int c = tid + i * 256;                 // 1024 chunks A
            int row = c >> 3, cc = (c & 7) * 4;
            cp16(a + row * SA + cc, U + (size_t)(m0 + row) * NREC + k0 + cc);
        }
        #pragma unroll
        for (int i = 0; i < 4; i++) {
            int c = tid + i * 256;                 // 1024 chunks each B
            int row = c >> 5, cc = (c & 31) * 4;
            size_t go = (size_t)(k0 + row) * HID + n0 + cc;
            cp16(br + row * SB + cc, BreP + go);
            cp16(bi + row * SB + cc, BimP + go);
        }
    };

    const int NKT = NREC / BK;   // 32
    loadStage(0, 0); cp_commit();
    loadStage(1, BK); cp_commit();

    for (int kt = 0; kt < NKT; kt++) {
        if (kt + 2 < NKT) cp_wait1(); else cp_wait0();
        __syncthreads();
        if (kt + 2 < NKT) { loadStage((kt + 2) % 3, (kt + 2) * BK); cp_commit(); }

        int s = kt % 3;
        const uint32_t* a  = (const uint32_t*)(sA  + s * ST);
        const uint32_t* br = (const uint32_t*)(sBr + s * ST);
        const uint32_t* bi = (const uint32_t*)(sBi + s * ST);
        #pragma unroll
        for (int ks = 0; ks < 4; ks++) {
            int kk = ks * 8;
            uint32_t af[4][4];
            #pragma unroll
            for (int i = 0; i < 4; i++) {
                int r = wm + i * 16 + g;
                af[i][0] = a[r * SA + kk + t];
                af[i][1] = a[(r + 8) * SA + kk + t];
                af[i][2] = a[r * SA + kk + t + 4];
                af[i][3] = a[(r + 8) * SA + kk + t + 4];
            }
            uint4 br0 = *(const uint4*)(br + (kk + t) * SB + wn + 4 * g);
            uint4 br1 = *(const uint4*)(br + (kk + t + 4) * SB + wn + 4 * g);
            uint4 bi0 = *(const uint4*)(bi + (kk + t) * SB + wn + 4 * g);
            uint4 bi1 = *(const uint4*)(bi + (kk + t + 4) * SB + wn + 4 * g);
            uint32_t b0[4] = {br0.x, br0.y, br0.z, br0.w};
            uint32_t b1[4] = {br1.x, br1.y, br1.z, br1.w};
            uint32_t c0[4] = {bi0.x, bi0.y, bi0.z, bi0.w};
            uint32_t c1[4] = {bi1.x, bi1.y, bi1.z, bi1.w};
            #pragma unroll
            for (int i = 0; i < 4; i++)
                #pragma unroll
                for (int j = 0; j < 4; j++) {
                    mma8(ar[i][j], af[i], b0[j], b1[j]);
                    mma8(ai[i][j], af[i], c0[j], c1[j]);
                }
        }
        __syncthreads();
    }

    // tables for this block's 128 H-columns (smem free now)
    float* sLr = smem;
    float* sLi = smem + 128;
    float* sG  = smem + 256;
    if (tid < 128) {
        int h = n0 + tid;
        float e = expf(-expf(nu[h]));
        float th = theta[h];
        sLr[tid] = e * cosf(th);
        sLi[tid] = e * sinf(th);
        sG[tid]  = gam[h];
    }
    __syncthreads();

    #pragma unroll
    for (int i = 0; i < 4; i++) {
        int r0 = m0 + wm + i * 16 + g;
        #pragma unroll
        for (int j = 0; j < 4; j++) {
            int cl = wn + j * 8 + 2 * t;
            float lr0 = sLr[cl],     li0 = sLi[cl],     g0 = sG[cl];
            float lr1 = sLr[cl + 1], li1 = sLi[cl + 1], g1 = sG[cl + 1];
            #pragma unroll
            for (int rr = 0; rr < 2; rr++) {
                int r = r0 + rr * 8;
                size_t off = (size_t)r * HID + n0 + cl;
                float2 sre = *(const float2*)(Sre + off);
                float2 sim = *(const float2*)(Sim + off);
                float tr0 = ar[i][j][rr * 2 + 0], tr1 = ar[i][j][rr * 2 + 1];
                float ti0 = ai[i][j][rr * 2 + 0], ti1 = ai[i][j][rr * 2 + 1];
                float2 ore, oim;
                ore.x = sre.x * lr0 - sim.x * li0 + g0 * tr0;
                ore.y = sre.y * lr1 - sim.y * li1 + g1 * tr1;
                oim.x = sre.x * li0 + sim.x * lr0 + g0 * ti0;
                oim.y = sre.y * li1 + sim.y * lr1 + g1 * ti1;
                *(float2*)(Xre + off) = ore;
                *(float2*)(Xim + off) = oim;
            }
        }
    }
}

// =====================================================================================
// GEMM2: Y = Xre @ Cre' + Xim @ Cimneg' + D*U   (Cim pre-negated)
// block tile 128x128, 256 threads, warp 64x32, 3-stage cp.async
// =====================================================================================
__global__ __launch_bounds__(256, 1) void lru_g2(
    const float* __restrict__ Xre, const float* __restrict__ Xim,
    const float* __restrict__ CreP, const float* __restrict__ CimP,
    const float* __restrict__ Dv,  const float* __restrict__ U,
    float* __restrict__ Y)
{
    const int n0 = blockIdx.x * 128;     // NREC
    const int m0 = blockIdx.y * 128;     // BATCH
    const int tid = threadIdx.x, warp = tid >> 5, lane = tid & 31;
    const int g = lane >> 2, t = lane & 3;
    const int wm = (warp >> 2) * 64, wn = (warp & 3) * 32;

    // stage layout: [Are | Aim | Bre | Bim] x 3
    const int ST = 2 * A_TILE + 2 * B_TILE;        // 17920 floats (71680 B)
    float* sAr = smem;
    float* sAi = smem + A_TILE;
    float* sBr = smem + 2 * A_TILE;
    float* sBi = smem + 2 * A_TILE + B_TILE;

    float acc[4][4][4];
    #pragma unroll
    for (int i = 0; i < 4; i++)
        #pragma unroll
        for (int j = 0; j < 4; j++)
            #pragma unroll
            for (int r = 0; r < 4; r++) acc[i][j][r] = 0.f;

    auto loadStage = [&](int s, int k0) {
        float* a0 = sAr + s * ST;
        float* a1 = sAi + s * ST;
        float* b0 = sBr + s * ST;
        float* b1 = sBi + s * ST;
        #pragma unroll
        for (int i = 0; i < 4; i++) {
            int c = tid + i * 256;
            int row = c >> 3, cc = (c & 7) * 4;
            size_t go = (size_t)(m0 + row) * HID + k0 + cc;
            cp16(a0 + row * SA + cc, Xre + go);
            cp16(a1 + row * SA + cc, Xim + go);
        }
        #pragma unroll
        for (int i = 0; i < 4; i++) {
            int c = tid + i * 256;
            int row = c >> 5, cc = (c & 31) * 4;
            size_t go = (size_t)(k0 + row) * NREC + n0 + cc;
            cp16(b0 + row * SB + cc, CreP + go);
            cp16(b1 + row * SB + cc, CimP + go);
        }
    };

    const int NKT = HID / BK;    // 64
    loadStage(0, 0); cp_commit();
    loadStage(1, BK); cp_commit();

    for (int kt = 0; kt < NKT; kt++) {
        if (kt + 2 < NKT) cp_wait1(); else cp_wait0();
        __syncthreads();
        if (kt + 2 < NKT) { loadStage((kt + 2) % 3, (kt + 2) * BK); cp_commit(); }

        int s = kt % 3;
        const uint32_t* a0 = (const uint32_t*)(sAr + s * ST);
        const uint32_t* a1 = (const uint32_t*)(sAi + s * ST);
        const uint32_t* b0p = (const uint32_t*)(sBr + s * ST);
        const uint32_t* b1p = (const uint32_t*)(sBi + s * ST);
        #pragma unroll
        for (int ks = 0; ks < 4; ks++) {
            int kk = ks * 8;
            uint32_t arf[4][4], aif[4][4];
            #pragma unroll
            for (int i = 0; i < 4; i++) {
                int r = wm + i * 16 + g;
                arf[i][0] = a0[r * SA + kk + t];
                arf[i][1] = a0[(r + 8) * SA + kk + t];
                arf[i][2] = a0[r * SA + kk + t + 4];
                arf[i][3] = a0[(r + 8) * SA + kk + t + 4];
                aif[i][0] = a1[r * SA + kk + t];
                aif[i][1] = a1[(r + 8) * SA + kk + t];
                aif[i][2] = a1[r * SA + kk + t + 4];
                aif[i][3] = a1[(r + 8) * SA + kk + t + 4];
            }
            uint4 vr0 = *(const uint4*)(b0p + (kk + t) * SB + wn + 4 * g);
            uint4 vr1 = *(const uint4*)(b0p + (kk + t + 4) * SB + wn + 4 * g);
            uint4 vi0 = *(const uint4*)(b1p + (kk + t) * SB + wn + 4 * g);
            uint4 vi1 = *(const uint4*)(b1p + (kk + t + 4) * SB + wn + 4 * g);
            uint32_t br0[4] = {vr0.x, vr0.y, vr0.z, vr0.w};
            uint32_t br1[4] = {vr1.x, vr1.y, vr1.z, vr1.w};
            uint32_t bi0[4] = {vi0.x, vi0.y, vi0.z, vi0.w};
            uint32_t bi1[4] = {vi1.x, vi1.y, vi1.z, vi1.w};
            #pragma unroll
            for (int i = 0; i < 4; i++)
                #pragma unroll
                for (int j = 0; j < 4; j++) {
                    mma8(acc[i][j], arf[i], br0[j], br1[j]);
                    mma8(acc[i][j], aif[i], bi0[j], bi1[j]);
                }
        }
        __syncthreads();
    }

    // epilogue: y = acc + D[c]*U[r,c]
    #pragma unroll
    for (int i = 0; i < 4; i++) {
        int r0 = m0 + wm + i * 16 + g;
        #pragma unroll
        for (int j = 0; j < 4; j++) {
            int cl = wn + j * 8 + 2 * t;
            int c  = n0 + cl;
            float d0 = Dv[c], d1 = Dv[c + 1];
            #pragma unroll
            for (int rr = 0; rr < 2; rr++) {
                int r = r0 + rr * 8;
                size_t off = (size_t)r * NREC + c;
                float2 u = *(const float2*)(U + off);
                float2 o;
                o.x = acc[i][j][rr * 2 + 0] + d0 * u.x;
                o.y = acc[i][j][rr * 2 + 1] + d1 * u.y;
                *(float2*)(Y + off) = o;
            }
        }
    }
}

// =====================================================================================
extern "C" void kernel_launch(void* const* d_in, const int* in_sizes, int n_in,
                              void* d_out, int out_size)
{
    const float* U   = (const float*)d_in[0];
    const float* Sre = (const float*)d_in[1];
    const float* Sim = (const float*)d_in[2];
    const float* Bre = (const float*)d_in[3];
    const float* Bim = (const float*)d_in[4];
    const float* Cre = (const float*)d_in[5];
    const float* Cim = (const float*)d_in[6];
    const float* Dv  = (const float*)d_in[7];
    const float* nu  = (const float*)d_in[8];
    const float* th  = (const float*)d_in[9];
    const float* gm  = (const float*)d_in[10];

    float* Y   = (float*)d_out;
    float* Xre = Y + (size_t)BATCH * NREC;
    float* Xim = Xre + (size_t)BATCH * HID;

    float *Bp = nullptr, *Cp = nullptr;
    cudaGetSymbolAddress((void**)&Bp, g_B);
    cudaGetSymbolAddress((void**)&Cp, g_C);

    // weight prep: rna-round + n-permute (+ negate Cim)
    const int totB = NREC * HID, totC = HID * NREC;
    prep_w<<<(totB + 255) / 256, 256>>>(Bre, Bp,        HID,  totB, 1.f);
    prep_w<<<(totB + 255) / 256, 256>>>(Bim, Bp + totB, HID,  totB, 1.f);
    prep_w<<<(totC + 255) / 256, 256>>>(Cre, Cp,        NREC, totC, 1.f);
    prep_w<<<(totC + 255) / 256, 256>>>(Cim, Cp + totC, NREC, totC, -1.f);

    const int smem1 = 3 * (A_TILE + 2 * B_TILE) * (int)sizeof(float);      // 159744
    const int smem2 = 3 * (2 * A_TILE + 2 * B_TILE) * (int)sizeof(float);  // 215040
    cudaFuncSetAttribute(lru_g1, cudaFuncAttributeMaxDynamicSharedMemorySize, smem1);
    cudaFuncSetAttribute(lru_g2, cudaFuncAttributeMaxDynamicSharedMemorySize, smem2);

    dim3 g1(HID / 128, BATCH / 128);     // 16 x 64
    lru_g1<<<g1, 256, smem1>>>(U, Bp, Bp + totB, Sre, Sim, nu, th, gm, Xre, Xim);

    dim3 g2(NREC / 128, BATCH / 128);    // 8 x 64
    lru_g2<<<g2, 256, smem2>>>(Xre, Xim, Cp, Cp + totC, Dv, U, Y);
}

// round 4
// speedup vs baseline: 1.6229x; 1.0195x over previous
#include <cuda_runtime.h>
#include <cstdint>
#include <cstddef>

#define BATCH 8192
#define NREC  1024
#define HID   2048

#define BK 32
#define SA 36     // A smem row stride (floats): 128 rows x (32+4)
#define SB 136    // B smem row stride (floats): 32 rows x (128+8)
#define A_TILE (128 * SA)   // 4608 floats
#define B_TILE (BK * SB)    // 4352 floats
#define ST (A_TILE + B_TILE) // 8960 floats per stage
#define SMEM_BYTES (3 * ST * (int)sizeof(float))   // 107520

extern __shared__ float smem[];

// ---------------- prepped weights (rna-rounded, n-permuted, Cim negated) ----
__device__ float g_B[2u * NREC * HID];             // [Bre'|Bim'] each [NREC k][HID n]
__device__ float g_C[2u * HID * NREC];             // [Cre' ; -Cim'] stacked [2*HID k][NREC n]

__device__ __forceinline__ uint32_t f2tf32(float x) {
    uint32_t r; asm("cvt.rna.tf32.f32 %0, %1;" : "=r"(r) : "f"(x)); return r;
}

__device__ __forceinline__ void mma8(float* d, const uint32_t* a, uint32_t b0, uint32_t b1) {
    asm volatile(
        "mma.sync.aligned.m16n8k8.row.col.f32.tf32.tf32.f32 "
        "{%0,%1,%2,%3}, {%4,%5,%6,%7}, {%8,%9}, {%0,%1,%2,%3};\n"
        : "+f"(d[0]), "+f"(d[1]), "+f"(d[2]), "+f"(d[3])
        : "r"(a[0]), "r"(a[1]), "r"(a[2]), "r"(a[3]), "r"(b0), "r"(b1));
}

__device__ __forceinline__ void cp16(float* s, const float* g) {
    uint32_t sa = (uint32_t)__cvta_generic_to_shared(s);
    asm volatile("cp.async.cg.shared.global [%0], [%1], 16;\n" :: "r"(sa), "l"(g));
}
__device__ __forceinline__ void cp_commit() { asm volatile("cp.async.commit_group;\n"); }
__device__ __forceinline__ void cp_wait1()  { asm volatile("cp.async.wait_group 1;\n"); }
__device__ __forceinline__ void cp_wait0()  { asm volatile("cp.async.wait_group 0;\n"); }

// ---------------- prep: rna-round, permute n within 32-blocks, negate Cim ----
// dst col (base+p) <- src col (base + (p&3)*8 + (p>>2)); one launch, grid.y = 4
__global__ __launch_bounds__(256) void prep_all(
    const float* __restrict__ B0, const float* __restrict__ B1,
    const float* __restrict__ C0, const float* __restrict__ C1,
    float* __restrict__ Bp, float* __restrict__ Cp)
{
    const int idx = blockIdx.x * 256 + threadIdx.x;
    const int z = blockIdx.y;
    const float* src; float* dst; int N; float sign = 1.f;
    if (z == 0)      { src = B0; dst = Bp;                          N = HID; }
    else if (z == 1) { src = B1; dst = Bp + (size_t)NREC * HID;     N = HID; }
    else if (z == 2) { src = C0; dst = Cp;                          N = NREC; }
    else             { src = C1; dst = Cp + (size_t)HID * NREC;     N = NREC; sign = -1.f; }
    const int row = idx / N, l = idx % N;
    const int base = l & ~31, p = l & 31;
    const int sl = base + ((p & 3) * 8) + (p >> 2);
    dst[idx] = __uint_as_float(f2tf32(sign * src[(size_t)row * N + sl]));
}

// =============================================================================
// GEMM1: T = U @ B{re|im}'  (z selects);  X{re|im} = f(S, T)
// 128x128 block, 256 thr, warp 64x32, 3-stage, 2 CTAs/SM
// =============================================================================
__global__ __launch_bounds__(256, 2) void lru_g1(
    const float* __restrict__ U,
    const float* __restrict__ Bp,
    const float* __restrict__ Sre, const float* __restrict__ Sim,
    const float* __restrict__ nu,  const float* __restrict__ theta,
    const float* __restrict__ gam,
    float* __restrict__ Xre, float* __restrict__ Xim)
{
    const int n0 = blockIdx.x * 128;     // HID
    const int m0 = blockIdx.y * 128;     // BATCH
    const int z  = blockIdx.z;
    const float* __restrict__ Bmat = Bp + (size_t)z * NREC * HID;

    const int tid = threadIdx.x, warp = tid >> 5, lane = tid & 31;
    const int g = lane >> 2, t = lane & 3;
    const int wm = (warp >> 2) * 64, wn = (warp & 3) * 32;

    float acc[4][4][4];
    #pragma unroll
    for (int i = 0; i < 4; i++)
        #pragma unroll
        for (int j = 0; j < 4; j++)
            #pragma unroll
            for (int r = 0; r < 4; r++) acc[i][j][r] = 0.f;

    auto loadStage = [&](int s, int k0) {
        float* a = smem + s * ST;
        float* b = a + A_TILE;
        #pragma unroll
        for (int i = 0; i < 4; i++) {
            int c = tid + i * 256;
            int row = c >> 3, cc = (c & 7) * 4;
            cp16(a + row * SA + cc, U + (size_t)(m0 + row) * NREC + k0 + cc);
        }
        #pragma unroll
        for (int i = 0; i < 4; i++) {
            int c = tid + i * 256;
            int row = c >> 5, cc = (c & 31) * 4;
            cp16(b + row * SB + cc, Bmat + (size_t)(k0 + row) * HID + n0 + cc);
        }
    };

    const int NKT = NREC / BK;   // 32
    loadStage(0, 0); cp_commit();
    loadStage(1, BK); cp_commit();

    for (int kt = 0; kt < NKT; kt++) {
        if (kt + 2 < NKT) cp_wait1(); else cp_wait0();
        __syncthreads();
        if (kt + 2 < NKT) { loadStage((kt + 2) % 3, (kt + 2) * BK); cp_commit(); }

        int s = kt % 3;
        const uint32_t* a = (const uint32_t*)(smem + s * ST);
        const uint32_t* b = a + A_TILE;
        #pragma unroll
        for (int ks = 0; ks < 4; ks++) {
            int kk = ks * 8;
            uint32_t af[4][4];
            #pragma unroll
            for (int i = 0; i < 4; i++) {
                int r = wm + i * 16 + g;
                af[i][0] = a[r * SA + kk + t];
                af[i][1] = a[(r + 8) * SA + kk + t];
                af[i][2] = a[r * SA + kk + t + 4];
                af[i][3] = a[(r + 8) * SA + kk + t + 4];
            }
            uint4 v0 = *(const uint4*)(b + (kk + t) * SB + wn + 4 * g);
            uint4 v1 = *(const uint4*)(b + (kk + t + 4) * SB + wn + 4 * g);
            uint32_t b0[4] = {v0.x, v0.y, v0.z, v0.w};
            uint32_t b1[4] = {v1.x, v1.y, v1.z, v1.w};
            #pragma unroll
            for (int i = 0; i < 4; i++)
                #pragma unroll
                for (int j = 0; j < 4; j++)
                    mma8(acc[i][j], af[i], b0[j], b1[j]);
        }
        __syncthreads();
    }

    // tables for this block's 128 H-columns
    float* sLr = smem;
    float* sLi = smem + 128;
    float* sG  = smem + 256;
    if (tid < 128) {
        int h = n0 + tid;
        float e = expf(-expf(nu[h]));
        float th = theta[h];
        sLr[tid] = e * cosf(th);
        sLi[tid] = e * sinf(th);
        sG[tid]  = gam[h];
    }
    __syncthreads();

    float* __restrict__ Xout = z ? Xim : Xre;
    #pragma unroll
    for (int i = 0; i < 4; i++) {
        int r0 = m0 + wm + i * 16 + g;
        #pragma unroll
        for (int j = 0; j < 4; j++) {
            int cl = wn + j * 8 + 2 * t;
            float lr0 = sLr[cl],     li0 = sLi[cl],     g0 = sG[cl];
            float lr1 = sLr[cl + 1], li1 = sLi[cl + 1], g1 = sG[cl + 1];
            #pragma unroll
            for (int rr = 0; rr < 2; rr++) {
                int r = r0 + rr * 8;
                size_t off = (size_t)r * HID + n0 + cl;
                float2 sre = *(const float2*)(Sre + off);
                float2 sim = *(const float2*)(Sim + off);
                float t0 = acc[i][j][rr * 2 + 0], t1 = acc[i][j][rr * 2 + 1];
                float2 o;
                if (z == 0) {
                    o.x = sre.x * lr0 - sim.x * li0 + g0 * t0;
                    o.y = sre.y * lr1 - sim.y * li1 + g1 * t1;
                } else {
                    o.x = sre.x * li0 + sim.x * lr0 + g0 * t0;
                    o.y = sre.y * li1 + sim.y * lr1 + g1 * t1;
                }
                *(float2*)(Xout + off) = o;
            }
        }
    }
}

// =============================================================================
// GEMM2: Y = [Xre|Xim] @ [Cre'; -Cim'] + D*U   — single GEMM, K = 4096
// =============================================================================
__global__ __launch_bounds__(256, 2) void lru_g2(
    const float* __restrict__ Xre, const float* __restrict__ Xim,
    const float* __restrict__ Cp,
    const float* __restrict__ Dv,  const float* __restrict__ U,
    float* __restrict__ Y)
{
    const int n0 = blockIdx.x * 128;     // NREC
    const int m0 = blockIdx.y * 128;     // BATCH
    const int tid = threadIdx.x, warp = tid >> 5, lane = tid & 31;
    const int g = lane >> 2, t = lane & 3;
    const int wm = (warp >> 2) * 64, wn = (warp & 3) * 32;

    float acc[4][4][4];
    #pragma unroll
    for (int i = 0; i < 4; i++)
        #pragma unroll
        for (int j = 0; j < 4; j++)
            #pragma unroll
            for (int r = 0; r < 4; r++) acc[i][j][r] = 0.f;

    auto loadStage = [&](int s, int k0) {
        float* a = smem + s * ST;
        float* b = a + A_TILE;
        const float* Asrc = (k0 < HID) ? Xre : Xim;
        const int ka = k0 & (HID - 1);
        #pragma unroll
        for (int i = 0; i < 4; i++) {
            int c = tid + i * 256;
            int row = c >> 3, cc = (c & 7) * 4;
            cp16(a + row * SA + cc, Asrc + (size_t)(m0 + row) * HID + ka + cc);
        }
        #pragma unroll
        for (int i = 0; i < 4; i++) {
            int c = tid + i * 256;
            int row = c >> 5, cc = (c & 31) * 4;
            cp16(b + row * SB + cc, Cp + (size_t)(k0 + row) * NREC + n0 + cc);
        }
    };

    const int NKT = (2 * HID) / BK;    // 128
    loadStage(0, 0); cp_commit();
    loadStage(1, BK); cp_commit();

    for (int kt = 0; kt < NKT; kt++) {
        if (kt + 2 < NKT) cp_wait1(); else cp_wait0();
        __syncthreads();
        if (kt + 2 < NKT) { loadStage((kt + 2) % 3, (kt + 2) * BK); cp_commit(); }

        int s = kt % 3;
        const uint32_t* a = (const uint32_t*)(smem + s * ST);
        const uint32_t* b = a + A_TILE;
        #pragma unroll
        for (int ks = 0; ks < 4; ks++) {
            int kk = ks * 8;
            uint32_t af[4][4];
            #pragma unroll
            for (int i = 0; i < 4; i++) {
                int r = wm + i * 16 + g;
                af[i][0] = a[r * SA + kk + t];
                af[i][1] = a[(r + 8) * SA + kk + t];
                af[i][2] = a[r * SA + kk + t + 4];
                af[i][3] = a[(r + 8) * SA + kk + t + 4];
            }
            uint4 v0 = *(const uint4*)(b + (kk + t) * SB + wn + 4 * g);
            uint4 v1 = *(const uint4*)(b + (kk + t + 4) * SB + wn + 4 * g);
            uint32_t b0[4] = {v0.x, v0.y, v0.z, v0.w};
            uint32_t b1[4] = {v1.x, v1.y, v1.z, v1.w};
            #pragma unroll
            for (int i = 0; i < 4; i++)
                #pragma unroll
                for (int j = 0; j < 4; j++)
                    mma8(acc[i][j], af[i], b0[j], b1[j]);
        }
        __syncthreads();
    }

    // epilogue: y = acc + D[c]*U[r,c]
    #pragma unroll
    for (int i = 0; i < 4; i++) {
        int r0 = m0 + wm + i * 16 + g;
        #pragma unroll
        for (int j = 0; j < 4; j++) {
            int cl = wn + j * 8 + 2 * t;
            int c  = n0 + cl;
            float d0 = Dv[c], d1 = Dv[c + 1];
            #pragma unroll
            for (int rr = 0; rr < 2; rr++) {
                int r = r0 + rr * 8;
                size_t off = (size_t)r * NREC + c;
                float2 u = *(const float2*)(U + off);
                float2 o;
                o.x = acc[i][j][rr * 2 + 0] + d0 * u.x;
                o.y = acc[i][j][rr * 2 + 1] + d1 * u.y;
                *(float2*)(Y + off) = o;
            }
        }
    }
}

// =============================================================================
extern "C" void kernel_launch(void* const* d_in, const int* in_sizes, int n_in,
                              void* d_out, int out_size)
{
    const float* U   = (const float*)d_in[0];
    const float* Sre = (const float*)d_in[1];
    const float* Sim = (const float*)d_in[2];
    const float* Bre = (const float*)d_in[3];
    const float* Bim = (const float*)d_in[4];
    const float* Cre = (const float*)d_in[5];
    const float* Cim = (const float*)d_in[6];
    const float* Dv  = (const float*)d_in[7];
    const float* nu  = (const float*)d_in[8];
    const float* th  = (const float*)d_in[9];
    const float* gm  = (const float*)d_in[10];

    float* Y   = (float*)d_out;
    float* Xre = Y + (size_t)BATCH * NREC;
    float* Xim = Xre + (size_t)BATCH * HID;

    float *Bp = nullptr, *Cp = nullptr;
    cudaGetSymbolAddress((void**)&Bp, g_B);
    cudaGetSymbolAddress((void**)&Cp, g_C);

    const int tot = NREC * HID;   // per-matrix element count (same for B and C)
    dim3 gp(tot / 256, 4);
    prep_all<<<gp, 256>>>(Bre, Bim, Cre, Cim, Bp, Cp);

    cudaFuncSetAttribute(lru_g1, cudaFuncAttributeMaxDynamicSharedMemorySize, SMEM_BYTES);
    cudaFuncSetAttribute(lru_g2, cudaFuncAttributeMaxDynamicSharedMemorySize, SMEM_BYTES);

    dim3 g1(HID / 128, BATCH / 128, 2);    // 16 x 64 x 2
    lru_g1<<<g1, 256, SMEM_BYTES>>>(U, Bp, Sre, Sim, nu, th, gm, Xre, Xim);

    dim3 g2(NREC / 128, BATCH / 128);      // 8 x 64
    lru_g2<<<g2, 256, SMEM_BYTES>>>(Xre, Xim, Cp, Dv, U, Y);
}

// round 5
// speedup vs baseline: 1.6597x; 1.0227x over previous
#include <cuda_runtime.h>
#include <cstdint>
#include <cstddef>

#define BATCH 8192
#define NREC  1024
#define HID   2048

#define BK 32
#define SA 36       // A smem row stride (floats)
#define SB 136      // B smem row stride (floats)

// GEMM1: block 128M x 128N, fused re+im B tiles
#define A1_TILE (128 * SA)              // 4608 floats
#define B1_TILE (BK * SB)               // 4352 floats
#define ST1 (A1_TILE + 2 * B1_TILE)     // 13312 floats
#define SMEM1 (4 * ST1 * (int)sizeof(float))   // 212992

// GEMM2: block 256M x 128N
#define A2_TILE (256 * SA)              // 9216 floats
#define ST2 (A2_TILE + B1_TILE)         // 13568 floats
#define SMEM2 (4 * ST2 * (int)sizeof(float))   // 217088

extern __shared__ float smem[];

// ---------------- prepped weights (rna-rounded, n-permuted, Cim negated) ----
__device__ float g_B[2u * NREC * HID];        // [Bre'|Bim'] each [NREC k][HID n]
__device__ float g_C[2u * HID * NREC];        // [Cre' ; -Cim'] stacked [2*HID k][NREC n]

__device__ __forceinline__ uint32_t f2tf32(float x) {
    uint32_t r; asm("cvt.rna.tf32.f32 %0, %1;" : "=r"(r) : "f"(x)); return r;
}

__device__ __forceinline__ void mma8(float* d, const uint32_t* a, uint32_t b0, uint32_t b1) {
    asm volatile(
        "mma.sync.aligned.m16n8k8.row.col.f32.tf32.tf32.f32 "
        "{%0,%1,%2,%3}, {%4,%5,%6,%7}, {%8,%9}, {%0,%1,%2,%3};\n"
        : "+f"(d[0]), "+f"(d[1]), "+f"(d[2]), "+f"(d[3])
        : "r"(a[0]), "r"(a[1]), "r"(a[2]), "r"(a[3]), "r"(b0), "r"(b1));
}

__device__ __forceinline__ void cp16(float* s, const float* g) {
    uint32_t sa = (uint32_t)__cvta_generic_to_shared(s);
    asm volatile("cp.async.cg.shared.global [%0], [%1], 16;\n" :: "r"(sa), "l"(g));
}
__device__ __forceinline__ void cp_commit() { asm volatile("cp.async.commit_group;\n"); }
__device__ __forceinline__ void cp_wait0()  { asm volatile("cp.async.wait_group 0;\n"); }
__device__ __forceinline__ void cp_wait1()  { asm volatile("cp.async.wait_group 1;\n"); }
__device__ __forceinline__ void cp_wait2()  { asm volatile("cp.async.wait_group 2;\n"); }

// ---------------- prep: rna-round, permute n within 32-blocks, negate Cim ----
__global__ __launch_bounds__(256) void prep_all(
    const float* __restrict__ B0, const float* __restrict__ B1,
    const float* __restrict__ C0, const float* __restrict__ C1,
    float* __restrict__ Bp, float* __restrict__ Cp)
{
    const int idx = blockIdx.x * 256 + threadIdx.x;
    const int z = blockIdx.y;
    const float* src; float* dst; int N; float sign = 1.f;
    if (z == 0)      { src = B0; dst = Bp;                      N = HID; }
    else if (z == 1) { src = B1; dst = Bp + (size_t)NREC * HID; N = HID; }
    else if (z == 2) { src = C0; dst = Cp;                      N = NREC; }
    else             { src = C1; dst = Cp + (size_t)HID * NREC; N = NREC; sign = -1.f; }
    const int row = idx / N, l = idx % N;
    const int base = l & ~31, p = l & 31;
    const int sl = base + ((p & 3) * 8) + (p >> 2);
    dst[idx] = __uint_as_float(f2tf32(sign * src[(size_t)row * N + sl]));
}

// =============================================================================
// GEMM1 (fused): Tre = U @ Bre', Tim = U @ Bim'; X = f(S, T)
// block 128x128, 256 thr, 8 warps (2M x 4N), warp 64x32 per matrix, 4 stages
// =============================================================================
__global__ __launch_bounds__(256, 1) void lru_g1(
    const float* __restrict__ U,
    const float* __restrict__ Bp,
    const float* __restrict__ Sre, const float* __restrict__ Sim,
    const float* __restrict__ nu,  const float* __restrict__ theta,
    const float* __restrict__ gam,
    float* __restrict__ Xre, float* __restrict__ Xim)
{
    const int n0 = blockIdx.x * 128;     // HID
    const int m0 = blockIdx.y * 128;     // BATCH
    const float* __restrict__ Bre = Bp;
    const float* __restrict__ Bim = Bp + (size_t)NREC * HID;

    const int tid = threadIdx.x, warp = tid >> 5, lane = tid & 31;
    const int g = lane >> 2, t = lane & 3;
    const int wm = (warp >> 2) * 64, wn = (warp & 3) * 32;

    float ar[4][4][4], ai[4][4][4];
    #pragma unroll
    for (int i = 0; i < 4; i++)
        #pragma unroll
        for (int j = 0; j < 4; j++)
            #pragma unroll
            for (int r = 0; r < 4; r++) { ar[i][j][r] = 0.f; ai[i][j][r] = 0.f; }

    auto loadStage = [&](int s, int k0) {
        float* a  = smem + s * ST1;
        float* br = a + A1_TILE;
        float* bi = br + B1_TILE;
        #pragma unroll
        for (int i = 0; i < 4; i++) {
            int c = tid + i * 256;
            int row = c >> 3, cc = (c & 7) * 4;
            cp16(a + row * SA + cc, U + (size_t)(m0 + row) * NREC + k0 + cc);
        }
        #pragma unroll
        for (int i = 0; i < 4; i++) {
            int c = tid + i * 256;
            int row = c >> 5, cc = (c & 31) * 4;
            size_t go = (size_t)(k0 + row) * HID + n0 + cc;
            cp16(br + row * SB + cc, Bre + go);
            cp16(bi + row * SB + cc, Bim + go);
        }
    };

    const int NKT = NREC / BK;   // 32
    loadStage(0, 0); cp_commit();
    loadStage(1, BK); cp_commit();
    loadStage(2, 2 * BK); cp_commit();

    for (int kt = 0; kt < NKT; kt++) {
        if (kt + 2 < NKT) cp_wait2();
        else if (kt + 1 < NKT) cp_wait1();
        else cp_wait0();
        __syncthreads();
        if (kt + 3 < NKT) { loadStage((kt + 3) & 3, (kt + 3) * BK); cp_commit(); }

        const int s = kt & 3;
        const uint32_t* a  = (const uint32_t*)(smem + s * ST1);
        const uint32_t* br = a + A1_TILE;
        const uint32_t* bi = br + B1_TILE;
        #pragma unroll
        for (int ks = 0; ks < 4; ks++) {
            int kk = ks * 8;
            uint32_t af[4][4];
            #pragma unroll
            for (int i = 0; i < 4; i++) {
                int r = wm + i * 16 + g;
                af[i][0] = a[r * SA + kk + t];
                af[i][1] = a[(r + 8) * SA + kk + t];
                af[i][2] = a[r * SA + kk + t + 4];
                af[i][3] = a[(r + 8) * SA + kk + t + 4];
            }
            uint4 v0 = *(const uint4*)(br + (kk + t) * SB + wn + 4 * g);
            uint4 v1 = *(const uint4*)(br + (kk + t + 4) * SB + wn + 4 * g);
            uint4 w0 = *(const uint4*)(bi + (kk + t) * SB + wn + 4 * g);
            uint4 w1 = *(const uint4*)(bi + (kk + t + 4) * SB + wn + 4 * g);
            uint32_t b0[4] = {v0.x, v0.y, v0.z, v0.w};
            uint32_t b1[4] = {v1.x, v1.y, v1.z, v1.w};
            uint32_t c0[4] = {w0.x, w0.y, w0.z, w0.w};
            uint32_t c1[4] = {w1.x, w1.y, w1.z, w1.w};
            #pragma unroll
            for (int i = 0; i < 4; i++)
                #pragma unroll
                for (int j = 0; j < 4; j++) {
                    mma8(ar[i][j], af[i], b0[j], b1[j]);
                    mma8(ai[i][j], af[i], c0[j], c1[j]);
                }
        }
    }

    // tables for this block's 128 H-columns (stage-0 region; last compute stage was 3)
    float* sLr = smem;
    float* sLi = smem + 128;
    float* sG  = smem + 256;
    if (tid < 128) {
        int h = n0 + tid;
        float e = expf(-expf(nu[h]));
        float th = theta[h];
        sLr[tid] = e * cosf(th);
        sLi[tid] = e * sinf(th);
        sG[tid]  = gam[h];
    }
    __syncthreads();

    #pragma unroll
    for (int i = 0; i < 4; i++) {
        int r0 = m0 + wm + i * 16 + g;
        #pragma unroll
        for (int j = 0; j < 4; j++) {
            int cl = wn + j * 8 + 2 * t;
            float lr0 = sLr[cl],     li0 = sLi[cl],     g0 = sG[cl];
            float lr1 = sLr[cl + 1], li1 = sLi[cl + 1], g1 = sG[cl + 1];
            #pragma unroll
            for (int rr = 0; rr < 2; rr++) {
                int r = r0 + rr * 8;
                size_t off = (size_t)r * HID + n0 + cl;
                float2 sre = *(const float2*)(Sre + off);
                float2 sim = *(const float2*)(Sim + off);
                float tr0 = ar[i][j][rr * 2 + 0], tr1 = ar[i][j][rr * 2 + 1];
                float ti0 = ai[i][j][rr * 2 + 0], ti1 = ai[i][j][rr * 2 + 1];
                float2 ore, oim;
                ore.x = sre.x * lr0 - sim.x * li0 + g0 * tr0;
                ore.y = sre.y * lr1 - sim.y * li1 + g1 * tr1;
                oim.x = sre.x * li0 + sim.x * lr0 + g0 * ti0;
                oim.y = sre.y * li1 + sim.y * lr1 + g1 * ti1;
                *(float2*)(Xre + off) = ore;
                *(float2*)(Xim + off) = oim;
            }
        }
    }
}

// =============================================================================
// GEMM2: Y = [Xre|Xim] @ [Cre'; -Cim'] + D*U   — single GEMM, K = 4096
// block 256M x 128N, 256 thr, 8 warps (4M x 2N), warp 64x64, 4 stages
// =============================================================================
__global__ __launch_bounds__(256, 1) void lru_g2(
    const float* __restrict__ Xre, const float* __restrict__ Xim,
    const float* __restrict__ Cp,
    const float* __restrict__ Dv,  const float* __restrict__ U,
    float* __restrict__ Y)
{
    const int n0 = blockIdx.x * 128;     // NREC
    const int m0 = blockIdx.y * 256;     // BATCH
    const int tid = threadIdx.x, warp = tid >> 5, lane = tid & 31;
    const int g = lane >> 2, t = lane & 3;
    const int wm = (warp >> 1) * 64, wn = (warp & 1) * 64;

    float acc[4][8][4];
    #pragma unroll
    for (int i = 0; i < 4; i++)
        #pragma unroll
        for (int j = 0; j < 8; j++)
            #pragma unroll
            for (int r = 0; r < 4; r++) acc[i][j][r] = 0.f;

    auto loadStage = [&](int s, int k0) {
        float* a = smem + s * ST2;
        float* b = a + A2_TILE;
        const float* Asrc = (k0 < HID) ? Xre : Xim;
        const int ka = k0 & (HID - 1);
        #pragma unroll
        for (int i = 0; i < 8; i++) {
            int c = tid + i * 256;                 // 2048 chunks (256 rows)
            int row = c >> 3, cc = (c & 7) * 4;
            cp16(a + row * SA + cc, Asrc + (size_t)(m0 + row) * HID + ka + cc);
        }
        #pragma unroll
        for (int i = 0; i < 4; i++) {
            int c = tid + i * 256;                 // 1024 chunks
            int row = c >> 5, cc = (c & 31) * 4;
            cp16(b + row * SB + cc, Cp + (size_t)(k0 + row) * NREC + n0 + cc);
        }
    };

    const int NKT = (2 * HID) / BK;    // 128
    loadStage(0, 0); cp_commit();
    loadStage(1, BK); cp_commit();
    loadStage(2, 2 * BK); cp_commit();

    for (int kt = 0; kt < NKT; kt++) {
        if (kt + 2 < NKT) cp_wait2();
        else if (kt + 1 < NKT) cp_wait1();
        else cp_wait0();
        __syncthreads();
        if (kt + 3 < NKT) { loadStage((kt + 3) & 3, (kt + 3) * BK); cp_commit(); }

        const int s = kt & 3;
        const uint32_t* a = (const uint32_t*)(smem + s * ST2);
        const uint32_t* b = a + A2_TILE;
        #pragma unroll
        for (int ks = 0; ks < 4; ks++) {
            int kk = ks * 8;
            uint32_t af[4][4];
            #pragma unroll
            for (int i = 0; i < 4; i++) {
                int r = wm + i * 16 + g;
                af[i][0] = a[r * SA + kk + t];
                af[i][1] = a[(r + 8) * SA + kk + t];
                af[i][2] = a[r * SA + kk + t + 4];
                af[i][3] = a[(r + 8) * SA + kk + t + 4];
            }
            uint4 v0 = *(const uint4*)(b + (kk + t) * SB + wn + 4 * g);
            uint4 v1 = *(const uint4*)(b + (kk + t + 4) * SB + wn + 4 * g);
            uint4 v2 = *(const uint4*)(b + (kk + t) * SB + wn + 32 + 4 * g);
            uint4 v3 = *(const uint4*)(b + (kk + t + 4) * SB + wn + 32 + 4 * g);
            uint32_t b0[8] = {v0.x, v0.y, v0.z, v0.w, v2.x, v2.y, v2.z, v2.w};
            uint32_t b1[8] = {v1.x, v1.y, v1.z, v1.w, v3.x, v3.y, v3.z, v3.w};
            #pragma unroll
            for (int i = 0; i < 4; i++)
                #pragma unroll
                for (int j = 0; j < 8; j++)
                    mma8(acc[i][j], af[i], b0[j], b1[j]);
        }
    }

    // epilogue: y = acc + D[c]*U[r,c]   (cols j<4 in [wn, wn+32), j>=4 in [wn+32, wn+64))
    #pragma unroll
    for (int i = 0; i < 4; i++) {
        int r0 = m0 + wm + i * 16 + g;
        #pragma unroll
        for (int j = 0; j < 8; j++) {
            int cl = wn + (j >> 2) * 32 + (j & 3) * 8 + 2 * t;
            int c  = n0 + cl;
            float d0 = Dv[c], d1 = Dv[c + 1];
            #pragma unroll
            for (int rr = 0; rr < 2; rr++) {
                int r = r0 + rr * 8;
                size_t off = (size_t)r * NREC + c;
                float2 u = *(const float2*)(U + off);
                float2 o;
                o.x = acc[i][j][rr * 2 + 0] + d0 * u.x;
                o.y = acc[i][j][rr * 2 + 1] + d1 * u.y;
                *(float2*)(Y + off) = o;
            }
        }
    }
}

// =============================================================================
extern "C" void kernel_launch(void* const* d_in, const int* in_sizes, int n_in,
                              void* d_out, int out_size)
{
    const float* U   = (const float*)d_in[0];
    const float* Sre = (const float*)d_in[1];
    const float* Sim = (const float*)d_in[2];
    const float* Bre = (const float*)d_in[3];
    const float* Bim = (const float*)d_in[4];
    const float* Cre = (const float*)d_in[5];
    const float* Cim = (const float*)d_in[6];
    const float* Dv  = (const float*)d_in[7];
    const float* nu  = (const float*)d_in[8];
    const float* th  = (const float*)d_in[9];
    const float* gm  = (const float*)d_in[10];

    float* Y   = (float*)d_out;
    float* Xre = Y + (size_t)BATCH * NREC;
    float* Xim = Xre + (size_t)BATCH * HID;

    float *Bp = nullptr, *Cp = nullptr;
    cudaGetSymbolAddress((void**)&Bp, g_B);
    cudaGetSymbolAddress((void**)&Cp, g_C);

    const int tot = NREC * HID;
    dim3 gp(tot / 256, 4);
    prep_all<<<gp, 256>>>(Bre, Bim, Cre, Cim, Bp, Cp);

    cudaFuncSetAttribute(lru_g1, cudaFuncAttributeMaxDynamicSharedMemorySize, SMEM1);
    cudaFuncSetAttribute(lru_g2, cudaFuncAttributeMaxDynamicSharedMemorySize, SMEM2);

    dim3 g1(HID / 128, BATCH / 128);       // 16 x 64 = 1024 CTAs
    lru_g1<<<g1, 256, SMEM1>>>(U, Bp, Sre, Sim, nu, th, gm, Xre, Xim);

    dim3 g2(NREC / 128, BATCH / 256);      // 8 x 32 = 256 CTAs
    lru_g2<<<g2, 256, SMEM2>>>(Xre, Xim, Cp, Dv, U, Y);
}